// round 11
// baseline (speedup 1.0000x reference)
#include <cuda_runtime.h>
#include <cuda_bf16.h>
#include <cstdint>

#define T_LEN 16384
#define HID   128
#define G4    512   // 4*HID gate rows

// ---------------- scratch (static device globals; no allocation) -------------
// gx layout: [t][unit 0..127][gate i,f,g,o]
__device__ __align__(16) float g_gx[4u * T_LEN * G4];   // [l0f,l0b,l1f,l1b]
__device__ __align__(16) float g_h0[T_LEN * 2 * HID];   // layer0 out [t][256]
__device__ __align__(16) float g_h1[T_LEN * 2 * HID];   // layer1 out [t][256]

// ---------------- helpers ----------------------------------------------------
__device__ __forceinline__ void fma2(unsigned long long& d,
                                     unsigned long long a,
                                     unsigned long long b) {
    asm("fma.rn.f32x2 %0, %1, %2, %0;" : "+l"(d) : "l"(a), "l"(b));
}
__device__ __forceinline__ float unpack_sum(unsigned long long v) {
    float lo, hi;
    asm("mov.b64 {%0,%1}, %2;" : "=f"(lo), "=f"(hi) : "l"(v));
    return lo + hi;
}
__device__ __forceinline__ uint32_t smem_u32(const void* p) {
    uint32_t a;
    asm("{ .reg .u64 t; cvta.to.shared.u64 t, %1; cvt.u32.u64 %0, t; }"
        : "=r"(a) : "l"(p));
    return a;
}
__device__ __forceinline__ uint32_t mapa_u32(uint32_t addr, uint32_t r) {
    uint32_t out;
    asm("mapa.shared::cluster.u32 %0, %1, %2;" : "=r"(out) : "r"(addr), "r"(r));
    return out;
}
__device__ __forceinline__ void wait_bar_relaxed(uint32_t bar, unsigned par) {
    unsigned done;
    asm volatile(
        "{\n\t.reg .pred p;\n\t"
        "mbarrier.try_wait.parity.relaxed.cta.shared::cta.b64 p, [%1], %2, 0x989680;\n\t"
        "selp.b32 %0, 1, 0, p;\n\t}"
        : "=r"(done) : "r"(bar), "r"(par) : "memory");
    while (!done) {
        asm volatile(
            "{\n\t.reg .pred p;\n\t"
            "mbarrier.try_wait.parity.relaxed.cta.shared::cta.b64 p, [%1], %2, 0x989680;\n\t"
            "selp.b32 %0, 1, 0, p;\n\t}"
            : "=r"(done) : "r"(bar), "r"(par) : "memory");
    }
}

// ---------------- kernel 1: layer-0 input projection (IN=1) ------------------
__global__ void k_gx0(const float* __restrict__ x,
                      const float* __restrict__ wf, const float* __restrict__ bfi,
                      const float* __restrict__ bfh,
                      const float* __restrict__ wb, const float* __restrict__ bbi,
                      const float* __restrict__ bbh,
                      float* __restrict__ gxf, float* __restrict__ gxb) {
    unsigned idx = blockIdx.x * 256u + threadIdx.x;
    if (idx >= (unsigned)T_LEN * G4) return;
    unsigned t = idx >> 9, r = idx & 511u;             // r = gate*128 + unit
    unsigned dst = t * G4 + (r & 127u) * 4u + (r >> 7);
    float xv = x[t];
    gxf[dst] = xv * wf[r] + bfi[r] + bfh[r];
    gxb[dst] = xv * wb[r] + bbi[r] + bbh[r];
}

// ---------------- kernel 2: recurrent scan, 4-CTA cluster per direction ------
// Grid = 8 CTAs, cluster 4. Cluster 0 = fwd, cluster 1 = bwd.
// CTA rank owns units [32*rank, 32*rank+32). Warp w owns units 2w, 2w+1.
// Lane l: unit j=l&1, k-sixteenth e=l>>1 (8 k-floats for all 4 gates;
// 32 weight floats = 8 ull2 regs/thread). Reduce-scatter: 5 shfl; final gate
// on lane = e>>2. Writers (l<2) send h to 3 peers via DSMEM.
// DOUBLE-BUFFERED mbarriers (bar[s&1], count 96 = 3 peers x 32 units) prevent
// phase-substitution races across the 3 source CTAs.
__global__ void __launch_bounds__(512, 1) __cluster_dims__(4, 1, 1)
k_lstm4(const float* __restrict__ gx_f, const float* __restrict__ gx_b,
        const float* __restrict__ whh_f, const float* __restrict__ whh_b,
        float* __restrict__ hcat) {
    __shared__ alignas(16) float hbuf[2 * 144];   // [buf][quarter*36 + unit]
    __shared__ alignas(8) unsigned long long bar_rem[2];

    const int dir = blockIdx.x >> 2;
    uint32_t rank;
    asm("mov.u32 %0, %%cluster_ctarank;" : "=r"(rank));
    const float* gx  = dir ? gx_b  : gx_f;
    const float* whh = dir ? whh_b : whh_f;

    const int tid  = threadIdx.x;
    const int w    = tid >> 5;
    const int l    = tid & 31;
    const int j    = l & 1;                     // unit within warp
    const int e    = l >> 1;                    // k-sixteenth 0..15
    const int lu   = (w << 1) | j;              // local unit 0..31
    const int gu   = (int)rank * 32 + lu;       // global unit
    const int gate = e >> 2;                    // lane's final gate
    const bool wr  = (l < 2);                   // writer lane (e==0)

    // ---- stage weights: 4 gates x 8 floats (k slice e*8..e*8+7) = 32 regs ---
    ulonglong2 wv[4][2];
#pragma unroll
    for (int g = 0; g < 4; g++) {
        const ulonglong2* row = (const ulonglong2*)
            (whh + (size_t)(g * HID + gu) * HID + e * 8);
        wv[g][0] = row[0]; wv[g][1] = row[1];
    }

    // ---- init ----
    if (tid < 288) hbuf[tid] = 0.f;
    const uint32_t b0_a = smem_u32(&bar_rem[0]);
    const uint32_t b1_a = smem_u32(&bar_rem[1]);
    const uint32_t hb_a = smem_u32(hbuf);
    if (tid == 0) {
        asm volatile("mbarrier.init.shared.b64 [%0], %1;"
                     :: "r"(b0_a), "r"(96u) : "memory");
        asm volatile("mbarrier.init.shared.b64 [%0], %1;"
                     :: "r"(b1_a), "r"(96u) : "memory");
    }
    __syncthreads();

    uint32_t peer_hb[3], peer_b0[3], peer_b1[3];
#pragma unroll
    for (int p = 0; p < 3; p++) {
        uint32_t pr = (rank + 1u + (uint32_t)p) & 3u;
        peer_hb[p] = mapa_u32(hb_a, pr);
        peer_b0[p] = mapa_u32(b0_a, pr);
        peer_b1[p] = mapa_u32(b1_a, pr);
    }

    asm volatile("barrier.cluster.arrive.aligned;" ::: "memory");
    asm volatile("barrier.cluster.wait.aligned;" ::: "memory");

    float c = 0.f;
    const int t_first = dir ? (T_LEN - 1) : 0;
    float gx_next = gx[(size_t)t_first * G4 + gu * 4 + gate];

    for (int s = 0; s < T_LEN; ++s) {
        const int t = dir ? (T_LEN - 1 - s) : s;
        const float gxv = gx_next;
        const int rd = (s & 1) ^ 1;                   // buffer holding h(s-1)

        {   // prefetch next step's gx (off critical path)
            int t2 = dir ? (t - 1) : (t + 1);
            if (s == T_LEN - 1) t2 = t;
            gx_next = gx[(size_t)t2 * G4 + gu * 4 + gate];
        }

        // ---- wait for all 3 peers' h(s-1): bar[(s-1)&1], par ((s-1)>>1)&1 --
        if (s) {
            const int sb = (s - 1) & 1;
            wait_bar_relaxed(sb ? b1_a : b0_a, (unsigned)(((s - 1) >> 1) & 1));
        }

        // ---- matvec: this lane's 8-k slice for all 4 gates ----
        const ulonglong2* h2 = (const ulonglong2*)
            (hbuf + rd * 144 + (e >> 2) * 36 + (e & 3) * 8);
        ulonglong2 h0v = h2[0], h1v = h2[1];
        unsigned long long a0 = 0ull, a1 = 0ull, a2 = 0ull, a3 = 0ull;
        fma2(a0, wv[0][0].x, h0v.x); fma2(a0, wv[0][0].y, h0v.y);
        fma2(a1, wv[1][0].x, h0v.x); fma2(a1, wv[1][0].y, h0v.y);
        fma2(a2, wv[2][0].x, h0v.x); fma2(a2, wv[2][0].y, h0v.y);
        fma2(a3, wv[3][0].x, h0v.x); fma2(a3, wv[3][0].y, h0v.y);
        fma2(a0, wv[0][1].x, h1v.x); fma2(a0, wv[0][1].y, h1v.y);
        fma2(a1, wv[1][1].x, h1v.x); fma2(a1, wv[1][1].y, h1v.y);
        fma2(a2, wv[2][1].x, h1v.x); fma2(a2, wv[2][1].y, h1v.y);
        fma2(a3, wv[3][1].x, h1v.x); fma2(a3, wv[3][1].y, h1v.y);

        // ---- reduce-scatter over 16 e-lanes: 5 shfls ----
        float S0 = unpack_sum(a0);                    // i partial
        float S1 = unpack_sum(a1);                    // f
        float S2 = unpack_sum(a2);                    // g
        float S3 = unpack_sum(a3);                    // o
        float give0 = (e < 8) ? S2 : S0;
        float give1 = (e < 8) ? S3 : S1;
        float r0 = __shfl_xor_sync(0xFFFFFFFFu, give0, 16);
        float r1 = __shfl_xor_sync(0xFFFFFFFFu, give1, 16);
        float A  = ((e < 8) ? S0 : S2) + r0;          // lo-e: i, hi-e: g
        float B  = ((e < 8) ? S1 : S3) + r1;          // lo-e: f, hi-e: o
        float give2 = (e & 4) ? A : B;
        float r2 = __shfl_xor_sync(0xFFFFFFFFu, give2, 8);
        float C  = ((e & 4) ? B : A) + r2;            // gate e>>2 partial
        C += __shfl_xor_sync(0xFFFFFFFFu, C, 4);
        C += __shfl_xor_sync(0xFFFFFFFFu, C, 2);

        // ---- unified activation: tanh(x)=1-2/(e^{2x}+1) ----
        float arg = C + gxv;
        float ag  = (gate == 2) ? (2.f * arg) : arg;
        float ex  = __expf(ag);
        float th  = 1.f - __fdividef(2.f, ex + 1.f);  // tanh(ag/2)
        float res = (gate == 2) ? th : (0.5f + 0.5f * th);

        // ---- gather f,g,o to writer lanes (l<2, holding i) ----
        float fv = __shfl_sync(0xFFFFFFFFu, res, 8 + j);
        float gv = __shfl_sync(0xFFFFFFFFu, res, 16 + j);
        float ov = __shfl_sync(0xFFFFFFFFu, res, 24 + j);

        if (wr) {
            c = fv * c + res * gv;                    // res == i on writers
            float exc = __expf(2.f * c);
            float thc = 1.f - __fdividef(2.f, exc + 1.f);
            float h = ov * thc;

            const int woff = (s & 1) * 144 + (int)rank * 36 + lu;
            const uint32_t wb4 = (uint32_t)(woff * 4);
#pragma unroll
            for (int p = 0; p < 3; p++) {
                asm volatile("st.shared::cluster.f32 [%0], %1;"
                             :: "r"(peer_hb[p] + wb4), "f"(h) : "memory");
                uint32_t pb = (s & 1) ? peer_b1[p] : peer_b0[p];
                asm volatile(
                    "mbarrier.arrive.release.cluster.shared::cluster.b64 _, [%0];"
                    :: "r"(pb) : "memory");
            }
            hbuf[woff] = h;
            hcat[(size_t)t * (2 * HID) + dir * HID + gu] = h;
        }
        __syncthreads();                              // local h visible, WAR safe
    }

    asm volatile("barrier.cluster.arrive.aligned;" ::: "memory");
    asm volatile("barrier.cluster.wait.aligned;" ::: "memory");
}

// ---------------- kernel 3: layer-1 input projection GEMM --------------------
__global__ void __launch_bounds__(512)
k_gx1(const float* __restrict__ h0,
      const float* __restrict__ Wf, const float* __restrict__ bfi,
      const float* __restrict__ bfh,
      const float* __restrict__ Wb, const float* __restrict__ bbi,
      const float* __restrict__ bbh,
      float* __restrict__ gxf, float* __restrict__ gxb) {
    const int dir = blockIdx.y;
    const float* W  = dir ? Wb  : Wf;
    const float* bi = dir ? bbi : bfi;
    const float* bh = dir ? bbh : bfh;
    float* gx       = dir ? gxb : gxf;

    __shared__ float hs[32 * 256];
    const int t0 = blockIdx.x * 32;
    const int r  = threadIdx.x;                        // gate*128 + unit

    for (int idx = r; idx < 32 * 256; idx += 512)
        hs[idx] = h0[(size_t)t0 * 256 + idx];
    __syncthreads();

    float acc[32];
    const float bias = bi[r] + bh[r];
#pragma unroll
    for (int tt = 0; tt < 32; tt++) acc[tt] = bias;

    const float4* wrow = (const float4*)(W + (size_t)r * 256);
    for (int k4 = 0; k4 < 64; k4++) {
        float4 w4 = wrow[k4];
#pragma unroll
        for (int tt = 0; tt < 32; tt++) {
            float4 hv = *(const float4*)(hs + tt * 256 + k4 * 4);
            acc[tt] += w4.x * hv.x + w4.y * hv.y + w4.z * hv.z + w4.w * hv.w;
        }
    }
    const unsigned dst_r = (r & 127u) * 4u + (r >> 7); // [unit][gate]
#pragma unroll
    for (int tt = 0; tt < 32; tt++)
        gx[(size_t)(t0 + tt) * G4 + dst_r] = acc[tt];
}

// ---------------- kernel 4: FC head ------------------------------------------
__global__ void __launch_bounds__(128)
k_head(const float* __restrict__ h1,
       const float* __restrict__ fc1w, const float* __restrict__ fc1b,
       const float* __restrict__ fc2w, const float* __restrict__ fc2b,
       float* __restrict__ out) {
    __shared__ float hs[8 * 256];
    __shared__ float z[8 * 128];
    const int t0 = blockIdx.x * 8;
    const int j  = threadIdx.x;

    for (int idx = j; idx < 8 * 256; idx += 128)
        hs[idx] = h1[(size_t)t0 * 256 + idx];
    __syncthreads();

    float acc[8];
    const float b = fc1b[j];
#pragma unroll
    for (int tt = 0; tt < 8; tt++) acc[tt] = b;

    const float4* wrow = (const float4*)(fc1w + (size_t)j * 256);
    for (int k4 = 0; k4 < 64; k4++) {
        float4 w4 = wrow[k4];
#pragma unroll
        for (int tt = 0; tt < 8; tt++) {
            float4 hv = *(const float4*)(hs + tt * 256 + k4 * 4);
            acc[tt] += w4.x * hv.x + w4.y * hv.y + w4.z * hv.z + w4.w * hv.w;
        }
    }
#pragma unroll
    for (int tt = 0; tt < 8; tt++) {
        float a = acc[tt];
        z[tt * 128 + j] = a > 0.f ? a : 0.01f * a;
    }
    __syncthreads();

    const int wid  = j >> 5;
    const int lane = j & 31;
#pragma unroll
    for (int q = 0; q < 2; q++) {
        int tt = wid * 2 + q;
        const float* zz = z + tt * 128;
        float s = fc2w[lane]      * zz[lane]
                + fc2w[lane + 32] * zz[lane + 32]
                + fc2w[lane + 64] * zz[lane + 64]
                + fc2w[lane + 96] * zz[lane + 96];
#pragma unroll
        for (int off = 16; off > 0; off >>= 1)
            s += __shfl_down_sync(0xFFFFFFFFu, s, off);
        if (lane == 0)
            out[t0 + tt] = s + fc2b[0];
    }
}

// ---------------- launcher ---------------------------------------------------
extern "C" void kernel_launch(void* const* d_in, const int* in_sizes, int n_in,
                              void* d_out, int out_size) {
    const float* x        = (const float*)d_in[0];
    const float* w_ih_l0  = (const float*)d_in[1];
    const float* w_hh_l0  = (const float*)d_in[2];
    const float* b_ih_l0  = (const float*)d_in[3];
    const float* b_hh_l0  = (const float*)d_in[4];
    const float* w_ih_l0r = (const float*)d_in[5];
    const float* w_hh_l0r = (const float*)d_in[6];
    const float* b_ih_l0r = (const float*)d_in[7];
    const float* b_hh_l0r = (const float*)d_in[8];
    const float* w_ih_l1  = (const float*)d_in[9];
    const float* w_hh_l1  = (const float*)d_in[10];
    const float* b_ih_l1  = (const float*)d_in[11];
    const float* b_hh_l1  = (const float*)d_in[12];
    const float* w_ih_l1r = (const float*)d_in[13];
    const float* w_hh_l1r = (const float*)d_in[14];
    const float* b_ih_l1r = (const float*)d_in[15];
    const float* b_hh_l1r = (const float*)d_in[16];
    const float* fc1_w    = (const float*)d_in[17];
    const float* fc1_b    = (const float*)d_in[18];
    const float* fc2_w    = (const float*)d_in[19];
    const float* fc2_b    = (const float*)d_in[20];
    float* out = (float*)d_out;

    float *gx_base, *h0, *h1;
    cudaGetSymbolAddress((void**)&gx_base, g_gx);
    cudaGetSymbolAddress((void**)&h0, g_h0);
    cudaGetSymbolAddress((void**)&h1, g_h1);
    float* gx0f = gx_base;
    float* gx0b = gx_base + (size_t)1 * T_LEN * G4;
    float* gx1f = gx_base + (size_t)2 * T_LEN * G4;
    float* gx1b = gx_base + (size_t)3 * T_LEN * G4;

    k_gx0<<<(T_LEN * G4 + 255) / 256, 256>>>(x, w_ih_l0, b_ih_l0, b_hh_l0,
                                             w_ih_l0r, b_ih_l0r, b_hh_l0r,
                                             gx0f, gx0b);
    k_lstm4<<<8, 512>>>(gx0f, gx0b, w_hh_l0, w_hh_l0r, h0);
    k_gx1<<<dim3(T_LEN / 32, 2), 512>>>(h0, w_ih_l1, b_ih_l1, b_hh_l1,
                                        w_ih_l1r, b_ih_l1r, b_hh_l1r,
                                        gx1f, gx1b);
    k_lstm4<<<8, 512>>>(gx1f, gx1b, w_hh_l1, w_hh_l1r, h1);
    k_head<<<T_LEN / 8, 128>>>(h1, fc1_w, fc1_b, fc2_w, fc2_b, out);
}

// round 12
// speedup vs baseline: 1.8978x; 1.8978x over previous
#include <cuda_runtime.h>
#include <cuda_bf16.h>
#include <cstdint>

#define T_LEN 16384
#define HID   128
#define G4    512   // 4*HID gate rows

// ---------------- scratch (static device globals; no allocation) -------------
// gx layout: [t][unit 0..127][gate i,f,g,o]
__device__ __align__(16) float g_gx[4u * T_LEN * G4];   // [l0f,l0b,l1f,l1b]
__device__ __align__(16) float g_h0[T_LEN * 2 * HID];   // layer0 out [t][256]
__device__ __align__(16) float g_h1[T_LEN * 2 * HID];   // layer1 out [t][256]

// ---------------- helpers ----------------------------------------------------
__device__ __forceinline__ void fma2(unsigned long long& d,
                                     unsigned long long a,
                                     unsigned long long b) {
    asm("fma.rn.f32x2 %0, %1, %2, %0;" : "+l"(d) : "l"(a), "l"(b));
}
__device__ __forceinline__ float unpack_sum(unsigned long long v) {
    float lo, hi;
    asm("mov.b64 {%0,%1}, %2;" : "=f"(lo), "=f"(hi) : "l"(v));
    return lo + hi;
}
__device__ __forceinline__ uint32_t smem_u32(const void* p) {
    uint32_t a;
    asm("{ .reg .u64 t; cvta.to.shared.u64 t, %1; cvt.u32.u64 %0, t; }"
        : "=r"(a) : "l"(p));
    return a;
}
__device__ __forceinline__ uint32_t mapa_u32(uint32_t addr, uint32_t r) {
    uint32_t out;
    asm("mapa.shared::cluster.u32 %0, %1, %2;" : "=r"(out) : "r"(addr), "r"(r));
    return out;
}
__device__ __forceinline__ void wait_bar_relaxed(uint32_t bar, unsigned par) {
    unsigned done;
    asm volatile(
        "{\n\t.reg .pred p;\n\t"
        "mbarrier.try_wait.parity.relaxed.cta.shared::cta.b64 p, [%1], %2, 0x989680;\n\t"
        "selp.b32 %0, 1, 0, p;\n\t}"
        : "=r"(done) : "r"(bar), "r"(par) : "memory");
    while (!done) {
        asm volatile(
            "{\n\t.reg .pred p;\n\t"
            "mbarrier.try_wait.parity.relaxed.cta.shared::cta.b64 p, [%1], %2, 0x989680;\n\t"
            "selp.b32 %0, 1, 0, p;\n\t}"
            : "=r"(done) : "r"(bar), "r"(par) : "memory");
    }
}

// ---------------- kernel 1: layer-0 input projection (IN=1) ------------------
__global__ void k_gx0(const float* __restrict__ x,
                      const float* __restrict__ wf, const float* __restrict__ bfi,
                      const float* __restrict__ bfh,
                      const float* __restrict__ wb, const float* __restrict__ bbi,
                      const float* __restrict__ bbh,
                      float* __restrict__ gxf, float* __restrict__ gxb) {
    unsigned idx = blockIdx.x * 256u + threadIdx.x;
    if (idx >= (unsigned)T_LEN * G4) return;
    unsigned t = idx >> 9, r = idx & 511u;             // r = gate*128 + unit
    unsigned dst = t * G4 + (r & 127u) * 4u + (r >> 7);
    float xv = x[t];
    gxf[dst] = xv * wf[r] + bfi[r] + bfh[r];
    gxb[dst] = xv * wb[r] + bbi[r] + bbh[r];
}

// ---------------- kernel 2: partial-exchange recurrent scan ------------------
// 2-CTA cluster per direction (grid 4). CTA rank owns h units [64r, 64r+64).
// PARTIAL-SUM EXCHANGE: producer warps (8-15) compute the PEER's gate rows
// over THIS CTA's k-half (local h, no wait) and ship 64 v4 packets of
// {i,f,g,o} partials per unit + release arrive. Consumer warps (0-7) compute
// own rows over own k, wait (relaxed), then only add+act+cell remain.
// Thread map (both halves): warp-in-half wh, lane l: unit uu = wh*8+(l>>2),
// k-slice/gate e = l&3 (16 k floats, all 4 gates; 64 weight regs).
// Double-buffered pbuf + mbarriers (bar[s&1], parity (s>>1)&1, count 64).
__global__ void __launch_bounds__(512, 1) __cluster_dims__(2, 1, 1)
k_lstm2(const float* __restrict__ gx_f, const float* __restrict__ gx_b,
        const float* __restrict__ whh_f, const float* __restrict__ whh_b,
        float* __restrict__ hcat) {
    __shared__ alignas(16) float hbuf[2 * 80];    // own h, skewed: u + (u>>4)*4
    __shared__ alignas(16) float pbuf[2 * 256];   // peer partials [u][gate]
    __shared__ alignas(8) unsigned long long bar_rem[2];

    const int dir = blockIdx.x >> 1;
    uint32_t rank;
    asm("mov.u32 %0, %%cluster_ctarank;" : "=r"(rank));
    const float* gx  = dir ? gx_b  : gx_f;
    const float* whh = dir ? whh_b : whh_f;

    const int tid  = threadIdx.x;
    const int half = tid >> 8;                  // 0 consumer, 1 producer
    const int l    = tid & 31;
    const int wh   = (tid >> 5) & 7;            // warp within half
    const int uu   = (wh << 3) | (l >> 2);      // unit index in group 0..63
    const int e    = l & 3;                     // k-16-slice AND final gate
    const bool wr  = (e == 0);
    const uint32_t prank = rank ^ 1u;
    // producer computes PEER's rows; consumer computes OWN rows
    const int group = (half ? (int)prank : (int)rank) * 64;
    const int gu_c  = (int)rank * 64 + uu;      // consumer's global unit

    // ---- stage weights: 4 gates x 16 k floats (own-k slice) = 64 regs ----
    ulonglong2 wv[4][4];
    const int kbase = (int)rank * 64 + e * 16;
#pragma unroll
    for (int g = 0; g < 4; g++) {
        const ulonglong2* p = (const ulonglong2*)
            (whh + (size_t)(g * HID + group + uu) * HID + kbase);
        wv[g][0] = p[0]; wv[g][1] = p[1]; wv[g][2] = p[2]; wv[g][3] = p[3];
    }

    // ---- init ----
    if (tid < 160) hbuf[tid] = 0.f;
    const uint32_t b0_a = smem_u32(&bar_rem[0]);
    const uint32_t b1_a = smem_u32(&bar_rem[1]);
    const uint32_t pb_a = smem_u32(pbuf);
    if (tid == 0) {
        asm volatile("mbarrier.init.shared.b64 [%0], %1;"
                     :: "r"(b0_a), "r"(64u) : "memory");
        asm volatile("mbarrier.init.shared.b64 [%0], %1;"
                     :: "r"(b1_a), "r"(64u) : "memory");
    }
    __syncthreads();

    const uint32_t peer_pb = mapa_u32(pb_a, prank);
    const uint32_t peer_b0 = mapa_u32(b0_a, prank);
    const uint32_t peer_b1 = mapa_u32(b1_a, prank);

    asm volatile("barrier.cluster.arrive.aligned;" ::: "memory");
    asm volatile("barrier.cluster.wait.aligned;" ::: "memory");

    float c = 0.f;
    const int t_first = dir ? (T_LEN - 1) : 0;
    float gx_next = 0.f;
    if (half == 0)
        gx_next = gx[(size_t)t_first * G4 + gu_c * 4 + e];

    for (int s = 0; s < T_LEN; ++s) {
        const int t  = dir ? (T_LEN - 1 - s) : s;
        const int rd = (s & 1) ^ 1;                   // buffer holding h(s-1)
        const int sb = s & 1;
        const float gxv = gx_next;

        if (half == 0) {                              // prefetch next gx
            int t2 = dir ? (t - 1) : (t + 1);
            if (s == T_LEN - 1) t2 = t;
            gx_next = gx[(size_t)t2 * G4 + gu_c * 4 + e];
        }

        // ---- dot: this lane's 16-k slice of OWN h, all 4 gates ----
        const ulonglong2* h2 =
            (const ulonglong2*)(hbuf + rd * 80 + e * 20);
        ulonglong2 hv0 = h2[0], hv1 = h2[1], hv2 = h2[2], hv3 = h2[3];
        unsigned long long a0 = 0ull, a1 = 0ull, a2 = 0ull, a3 = 0ull;
        fma2(a0, wv[0][0].x, hv0.x); fma2(a0, wv[0][0].y, hv0.y);
        fma2(a1, wv[1][0].x, hv0.x); fma2(a1, wv[1][0].y, hv0.y);
        fma2(a2, wv[2][0].x, hv0.x); fma2(a2, wv[2][0].y, hv0.y);
        fma2(a3, wv[3][0].x, hv0.x); fma2(a3, wv[3][0].y, hv0.y);
        fma2(a0, wv[0][1].x, hv1.x); fma2(a0, wv[0][1].y, hv1.y);
        fma2(a1, wv[1][1].x, hv1.x); fma2(a1, wv[1][1].y, hv1.y);
        fma2(a2, wv[2][1].x, hv1.x); fma2(a2, wv[2][1].y, hv1.y);
        fma2(a3, wv[3][1].x, hv1.x); fma2(a3, wv[3][1].y, hv1.y);
        fma2(a0, wv[0][2].x, hv2.x); fma2(a0, wv[0][2].y, hv2.y);
        fma2(a1, wv[1][2].x, hv2.x); fma2(a1, wv[1][2].y, hv2.y);
        fma2(a2, wv[2][2].x, hv2.x); fma2(a2, wv[2][2].y, hv2.y);
        fma2(a3, wv[3][2].x, hv2.x); fma2(a3, wv[3][2].y, hv2.y);
        fma2(a0, wv[0][3].x, hv3.x); fma2(a0, wv[0][3].y, hv3.y);
        fma2(a1, wv[1][3].x, hv3.x); fma2(a1, wv[1][3].y, hv3.y);
        fma2(a2, wv[2][3].x, hv3.x); fma2(a2, wv[2][3].y, hv3.y);
        fma2(a3, wv[3][3].x, hv3.x); fma2(a3, wv[3][3].y, hv3.y);

        // ---- reduce-scatter over 4 e-lanes: 3 shfls; lane e ends with gate e
        float S0 = unpack_sum(a0);                    // i partial
        float S1 = unpack_sum(a1);                    // f
        float S2 = unpack_sum(a2);                    // g
        float S3 = unpack_sum(a3);                    // o
        float give0 = (e < 2) ? S2 : S0;
        float give1 = (e < 2) ? S3 : S1;
        float r0 = __shfl_xor_sync(0xFFFFFFFFu, give0, 2);
        float r1 = __shfl_xor_sync(0xFFFFFFFFu, give1, 2);
        float A  = ((e < 2) ? S0 : S2) + r0;
        float B  = ((e < 2) ? S1 : S3) + r1;
        float give2 = (e & 1) ? A : B;
        float r2 = __shfl_xor_sync(0xFFFFFFFFu, give2, 1);
        float C  = ((e & 1) ? B : A) + r2;            // gate e, own-k 64 sum
        const int base = l & ~3;

        if (half == 1) {
            // ---- producer: ship {i,f,g,o} partials for peer unit uu ----
            float p1 = __shfl_sync(0xFFFFFFFFu, C, base + 1);
            float p2 = __shfl_sync(0xFFFFFFFFu, C, base + 2);
            float p3 = __shfl_sync(0xFFFFFFFFu, C, base + 3);
            if (wr) {
                uint32_t addr = peer_pb + (uint32_t)((sb * 256 + uu * 4) * 4);
                asm volatile("st.shared::cluster.v4.f32 [%0], {%1, %2, %3, %4};"
                             :: "r"(addr), "f"(C), "f"(p1), "f"(p2), "f"(p3)
                             : "memory");
                uint32_t pb = sb ? peer_b1 : peer_b0;
                asm volatile(
                    "mbarrier.arrive.release.cluster.shared::cluster.b64 _, [%0];"
                    :: "r"(pb) : "memory");
            }
        } else {
            // ---- consumer: wait for peer partials, finish the step ----
            wait_bar_relaxed(sb ? b1_a : b0_a, (unsigned)((s >> 1) & 1));
            float pp = pbuf[sb * 256 + uu * 4 + e];
            float arg = C + pp + gxv;
            float ag  = (e == 2) ? (2.f * arg) : arg;
            float ex  = __expf(ag);
            float th  = 1.f - __fdividef(2.f, ex + 1.f);   // tanh(ag/2)
            float res = (e == 2) ? th : (0.5f + 0.5f * th);

            float fv = __shfl_sync(0xFFFFFFFFu, res, base + 1);
            float gv = __shfl_sync(0xFFFFFFFFu, res, base + 2);
            float ov = __shfl_sync(0xFFFFFFFFu, res, base + 3);

            if (wr) {
                c = fv * c + res * gv;                 // res == i on writer
                float exc = __expf(2.f * c);
                float thc = 1.f - __fdividef(2.f, exc + 1.f);
                float h = ov * thc;
                hbuf[sb * 80 + uu + (uu >> 4) * 4] = h;
                hcat[(size_t)t * (2 * HID) + dir * HID + gu_c] = h;
            }
        }
        __syncthreads();                               // h(s) visible to all
    }

    asm volatile("barrier.cluster.arrive.aligned;" ::: "memory");
    asm volatile("barrier.cluster.wait.aligned;" ::: "memory");
}

// ---------------- kernel 3: layer-1 input projection GEMM --------------------
__global__ void __launch_bounds__(512)
k_gx1(const float* __restrict__ h0,
      const float* __restrict__ Wf, const float* __restrict__ bfi,
      const float* __restrict__ bfh,
      const float* __restrict__ Wb, const float* __restrict__ bbi,
      const float* __restrict__ bbh,
      float* __restrict__ gxf, float* __restrict__ gxb) {
    const int dir = blockIdx.y;
    const float* W  = dir ? Wb  : Wf;
    const float* bi = dir ? bbi : bfi;
    const float* bh = dir ? bbh : bfh;
    float* gx       = dir ? gxb : gxf;

    __shared__ float hs[32 * 256];
    const int t0 = blockIdx.x * 32;
    const int r  = threadIdx.x;                        // gate*128 + unit

    for (int idx = r; idx < 32 * 256; idx += 512)
        hs[idx] = h0[(size_t)t0 * 256 + idx];
    __syncthreads();

    float acc[32];
    const float bias = bi[r] + bh[r];
#pragma unroll
    for (int tt = 0; tt < 32; tt++) acc[tt] = bias;

    const float4* wrow = (const float4*)(W + (size_t)r * 256);
    for (int k4 = 0; k4 < 64; k4++) {
        float4 w4 = wrow[k4];
#pragma unroll
        for (int tt = 0; tt < 32; tt++) {
            float4 hv = *(const float4*)(hs + tt * 256 + k4 * 4);
            acc[tt] += w4.x * hv.x + w4.y * hv.y + w4.z * hv.z + w4.w * hv.w;
        }
    }
    const unsigned dst_r = (r & 127u) * 4u + (r >> 7); // [unit][gate]
#pragma unroll
    for (int tt = 0; tt < 32; tt++)
        gx[(size_t)(t0 + tt) * G4 + dst_r] = acc[tt];
}

// ---------------- kernel 4: FC head ------------------------------------------
__global__ void __launch_bounds__(128)
k_head(const float* __restrict__ h1,
       const float* __restrict__ fc1w, const float* __restrict__ fc1b,
       const float* __restrict__ fc2w, const float* __restrict__ fc2b,
       float* __restrict__ out) {
    __shared__ float hs[8 * 256];
    __shared__ float z[8 * 128];
    const int t0 = blockIdx.x * 8;
    const int j  = threadIdx.x;

    for (int idx = j; idx < 8 * 256; idx += 128)
        hs[idx] = h1[(size_t)t0 * 256 + idx];
    __syncthreads();

    float acc[8];
    const float b = fc1b[j];
#pragma unroll
    for (int tt = 0; tt < 8; tt++) acc[tt] = b;

    const float4* wrow = (const float4*)(fc1w + (size_t)j * 256);
    for (int k4 = 0; k4 < 64; k4++) {
        float4 w4 = wrow[k4];
#pragma unroll
        for (int tt = 0; tt < 8; tt++) {
            float4 hv = *(const float4*)(hs + tt * 256 + k4 * 4);
            acc[tt] += w4.x * hv.x + w4.y * hv.y + w4.z * hv.z + w4.w * hv.w;
        }
    }
#pragma unroll
    for (int tt = 0; tt < 8; tt++) {
        float a = acc[tt];
        z[tt * 128 + j] = a > 0.f ? a : 0.01f * a;
    }
    __syncthreads();

    const int wid  = j >> 5;
    const int lane = j & 31;
#pragma unroll
    for (int q = 0; q < 2; q++) {
        int tt = wid * 2 + q;
        const float* zz = z + tt * 128;
        float s = fc2w[lane]      * zz[lane]
                + fc2w[lane + 32] * zz[lane + 32]
                + fc2w[lane + 64] * zz[lane + 64]
                + fc2w[lane + 96] * zz[lane + 96];
#pragma unroll
        for (int off = 16; off > 0; off >>= 1)
            s += __shfl_down_sync(0xFFFFFFFFu, s, off);
        if (lane == 0)
            out[t0 + tt] = s + fc2b[0];
    }
}

// ---------------- launcher ---------------------------------------------------
extern "C" void kernel_launch(void* const* d_in, const int* in_sizes, int n_in,
                              void* d_out, int out_size) {
    const float* x        = (const float*)d_in[0];
    const float* w_ih_l0  = (const float*)d_in[1];
    const float* w_hh_l0  = (const float*)d_in[2];
    const float* b_ih_l0  = (const float*)d_in[3];
    const float* b_hh_l0  = (const float*)d_in[4];
    const float* w_ih_l0r = (const float*)d_in[5];
    const float* w_hh_l0r = (const float*)d_in[6];
    const float* b_ih_l0r = (const float*)d_in[7];
    const float* b_hh_l0r = (const float*)d_in[8];
    const float* w_ih_l1  = (const float*)d_in[9];
    const float* w_hh_l1  = (const float*)d_in[10];
    const float* b_ih_l1  = (const float*)d_in[11];
    const float* b_hh_l1  = (const float*)d_in[12];
    const float* w_ih_l1r = (const float*)d_in[13];
    const float* w_hh_l1r = (const float*)d_in[14];
    const float* b_ih_l1r = (const float*)d_in[15];
    const float* b_hh_l1r = (const float*)d_in[16];
    const float* fc1_w    = (const float*)d_in[17];
    const float* fc1_b    = (const float*)d_in[18];
    const float* fc2_w    = (const float*)d_in[19];
    const float* fc2_b    = (const float*)d_in[20];
    float* out = (float*)d_out;

    float *gx_base, *h0, *h1;
    cudaGetSymbolAddress((void**)&gx_base, g_gx);
    cudaGetSymbolAddress((void**)&h0, g_h0);
    cudaGetSymbolAddress((void**)&h1, g_h1);
    float* gx0f = gx_base;
    float* gx0b = gx_base + (size_t)1 * T_LEN * G4;
    float* gx1f = gx_base + (size_t)2 * T_LEN * G4;
    float* gx1b = gx_base + (size_t)3 * T_LEN * G4;

    k_gx0<<<(T_LEN * G4 + 255) / 256, 256>>>(x, w_ih_l0, b_ih_l0, b_hh_l0,
                                             w_ih_l0r, b_ih_l0r, b_hh_l0r,
                                             gx0f, gx0b);
    k_lstm2<<<4, 512>>>(gx0f, gx0b, w_hh_l0, w_hh_l0r, h0);
    k_gx1<<<dim3(T_LEN / 32, 2), 512>>>(h0, w_ih_l1, b_ih_l1, b_hh_l1,
                                        w_ih_l1r, b_ih_l1r, b_hh_l1r,
                                        gx1f, gx1b);
    k_lstm2<<<4, 512>>>(gx1f, gx1b, w_hh_l1, w_hh_l1r, h1);
    k_head<<<T_LEN / 8, 128>>>(h1, fc1_w, fc1_b, fc2_w, fc2_b, out);
}